// round 15
// baseline (speedup 1.0000x reference)
#include <cuda_runtime.h>
#include <cuda_bf16.h>
#include <cstdint>

// MotionPrediction: B=65536, 3 cyclic-MoE layers, dims 256, 4 experts.
// out = sum_e c_e (.) (X @ W_e + b_e), ReLU on layers 1,2.
// HMMA mma.sync m16n8k16 bf16, hi/lo split (3 products) ~ fp32 accuracy.
// R14: R7 base (128-row tile, 512 thr, 4 stages, distance-3, per-chunk
// barriers) + fixed tail waits + non-volatile MMA asm.

#define BSZ  65536
#define NDIM 256

__device__ __align__(16) __nv_bfloat16 g_Whi[3 * 4 * NDIM * NDIM]; // [slot][chunk=e*8+kc][n256][k32]
__device__ __align__(16) __nv_bfloat16 g_Wlo[3 * 4 * NDIM * NDIM];
__device__ __align__(16) __nv_bfloat16 g_Ahi[BSZ * NDIM];
__device__ __align__(16) __nv_bfloat16 g_Alo[BSZ * NDIM];
__device__ __align__(16) __nv_bfloat16 g_Bhi[BSZ * NDIM];
__device__ __align__(16) __nv_bfloat16 g_Blo[BSZ * NDIM];
__device__ float4 g_coeff[BSZ];

// ---- SMEM map (bytes) ----
#define ASTR     528                    // A row stride (256 bf16 + pad)
#define SA_LO    67584                  // A_lo = A_hi + 128*528
#define SB_OFF   135168                 // 4 B stages
#define SB_STAGE 20480                  // per stage: hi 10240 + lo 10240
#define SB_LO    10240
#define BSTR     80                     // B row stride (32 bf16 + pad)
#define SBIAS    217088                 // 512 floats
#define SM_TOTAL 219136

// ---------------------------------------------------------------- helpers
__device__ __forceinline__ uint32_t smem_u32(const void* p) {
    uint32_t a;
    asm("{ .reg .u64 t; cvta.to.shared.u64 t, %1; cvt.u32.u64 %0, t; }"
        : "=r"(a) : "l"(p));
    return a;
}
__device__ __forceinline__ void ldsm4(uint32_t* r, uint32_t a) {
    asm volatile("ldmatrix.sync.aligned.m8n8.x4.shared.b16 {%0,%1,%2,%3}, [%4];"
                 : "=r"(r[0]), "=r"(r[1]), "=r"(r[2]), "=r"(r[3]) : "r"(a));
}
// Not volatile: register data deps enforce per-accumulator order; ptxas may
// interleave independent MMAs with ldsm and across chunk boundaries.
__device__ __forceinline__ void mma16816(float* d, const uint32_t* a,
                                         uint32_t b0, uint32_t b1) {
    asm("mma.sync.aligned.m16n8k16.row.col.f32.bf16.bf16.f32 "
        "{%0,%1,%2,%3}, {%4,%5,%6,%7}, {%8,%9}, {%0,%1,%2,%3};"
        : "+f"(d[0]), "+f"(d[1]), "+f"(d[2]), "+f"(d[3])
        : "r"(a[0]), "r"(a[1]), "r"(a[2]), "r"(a[3]), "r"(b0), "r"(b1));
}
__device__ __forceinline__ void cpa16(uint32_t s, const void* g) {
    asm volatile("cp.async.cg.shared.global [%0], [%1], 16;" :: "r"(s), "l"(g));
}
__device__ __forceinline__ void split_bf16(float v, unsigned short& h, unsigned short& l) {
    __nv_bfloat16 hb = __float2bfloat16_rn(v);
    float r = v - __bfloat162float(hb);
    h = __bfloat16_as_ushort(hb);
    l = __bfloat16_as_ushort(__float2bfloat16_rn(r));
}

// ---------------------------------------------------------------- coeff
__global__ void coeff_kernel(const float* __restrict__ phi) {
    int b = blockIdx.x * blockDim.x + threadIdx.x;
    if (b >= BSZ) return;
    const float TWO_OVER_PI = (float)(2.0 / 3.14159265358979323846);
    float w  = TWO_OVER_PI * phi[b];
    int  wi  = ((int)w) & 3;
    float w2 = w * w, w3 = w2 * w;
    float co[4];
    co[0] = -0.5f * w + w2 - 0.5f * w3;
    co[1] = -2.5f * w2 + 1.5f * w3;
    co[2] =  0.5f * w + 2.0f * w2 - 1.5f * w3;
    co[3] = -0.5f * w2 + 0.5f * w3;
    float c[4];
#pragma unroll
    for (int e = 0; e < 4; ++e) c[e] = co[(e - wi + 5) & 3];
    g_coeff[b] = make_float4(c[0], c[1], c[2], c[3]);
}

// ---------------------------------------------------------------- X convert
__global__ void convX_kernel(const float* __restrict__ X) {
    size_t i = ((size_t)blockIdx.x * 256 + threadIdx.x) * 4;
    float4 f = *(const float4*)(X + i);
    float v[4] = {f.x, f.y, f.z, f.w};
    unsigned short h[4], l[4];
#pragma unroll
    for (int p = 0; p < 4; ++p) split_bf16(v[p], h[p], l[p]);
    *(uint2*)(g_Ahi + i) = make_uint2((uint32_t)h[0] | ((uint32_t)h[1] << 16),
                                      (uint32_t)h[2] | ((uint32_t)h[3] << 16));
    *(uint2*)(g_Alo + i) = make_uint2((uint32_t)l[0] | ((uint32_t)l[1] << 16),
                                      (uint32_t)l[2] | ((uint32_t)l[3] << 16));
}

// ---------------------------------------------------------------- W convert
// W [4][256 k][256 n] f32 -> blocked [chunk=e*8+kc][n 256][k 32] bf16 hi/lo
__global__ void convW3_kernel(const float* __restrict__ Wa,
                              const float* __restrict__ Wb,
                              const float* __restrict__ Wc) {
    int i = blockIdx.x * 256 + threadIdx.x;     // 262144 per layer
    int slot = blockIdx.y;
    const float* W = (slot == 0) ? Wa : (slot == 1) ? Wb : Wc;
    int chunk = i >> 13;
    int n = (i >> 5) & 255;
    int k = i & 31;
    int e = chunk >> 3, kc = chunk & 7;
    float w = W[((e << 8) + kc * 32 + k) * NDIM + n];
    unsigned short h, l;
    split_bf16(w, h, l);
    g_Whi[(size_t)slot * 262144 + i] = __ushort_as_bfloat16(h);
    g_Wlo[(size_t)slot * 262144 + i] = __ushort_as_bfloat16(l);
}

// ---------------------------------------------------------------- B chunk load
__device__ __forceinline__ void load_chunkB(uint32_t dst,
                                            const __nv_bfloat16* __restrict__ sH,
                                            const __nv_bfloat16* __restrict__ sL,
                                            uint32_t soff) {
    cpa16(dst,         (const char*)sH + soff);
    cpa16(dst + SB_LO, (const char*)sL + soff);
}

// ---------------------------------------------------------------- layer
template <bool RELU, bool BF16OUT>
__global__ void __launch_bounds__(512, 1) layer_hmma(
    const __nv_bfloat16* __restrict__ Xhi,
    const __nv_bfloat16* __restrict__ Xlo,
    const __nv_bfloat16* __restrict__ Whi,
    const __nv_bfloat16* __restrict__ Wlo,
    const float* __restrict__ bias,
    __nv_bfloat16* __restrict__ Ohi,
    __nv_bfloat16* __restrict__ Olo,
    float* __restrict__ Out)
{
    extern __shared__ char smem[];
    const uint32_t sb = smem_u32(smem);
    const int tid = threadIdx.x, lane = tid & 31, wid = tid >> 5;
    const int mwarp = wid >> 1, nwarp = wid & 1;   // 8 M-warps x 2 N-warps
    const int mtile = blockIdx.x >> 1, ch = blockIdx.x & 1;
    const int rowbase = mtile << 7, colbase = ch << 7;

    // per-thread source offset within a W chunk (bytes): row (colbase+n), quad q
    const int bn = tid >> 2, bq = tid & 3;
    const uint32_t wsrc_off = (uint32_t)(colbase + bn) * 64 + bq * 16;
    const uint32_t bdst = sb + SB_OFF + bn * BSTR + bq * 16;   // + stage*SB_STAGE

    // A tile: 128 rows x 256 bf16 hi/lo via cp.async (group 0)
#pragma unroll
    for (int u = tid; u < 4096; u += 512) {
        int r = u >> 5, s = u & 31;
        cpa16(sb + r * ASTR + s * 16,         Xhi + (size_t)(rowbase + r) * NDIM + s * 8);
        cpa16(sb + SA_LO + r * ASTR + s * 16, Xlo + (size_t)(rowbase + r) * NDIM + s * 8);
    }
    asm volatile("cp.async.commit_group;" ::: "memory");
    // preload chunks 0,1,2 into stages 0,1,2
#pragma unroll
    for (int c = 0; c < 3; ++c) {
        load_chunkB(bdst + c * SB_STAGE,
                    Whi + (size_t)c * 8192, Wlo + (size_t)c * 8192, wsrc_off);
        asm volatile("cp.async.commit_group;" ::: "memory");
    }

    // bias -> smem: [e][128] for this col half
    ((float*)(smem + SBIAS))[tid] = bias[(tid >> 7) * NDIM + colbase + (tid & 127)];

    const int gr0 = rowbase + mwarp * 16 + (lane >> 2);
    const float4 cva = g_coeff[gr0];
    const float4 cvb = g_coeff[gr0 + 8];

    const int lrow = (lane & 7) + (((lane >> 3) & 1) << 3);
    const int lkof = (lane >> 4) << 3;
    const uint32_t aBase = sb + (mwarp * 16 + lrow) * ASTR + lkof * 2;
    const uint32_t bRow  = sb + SB_OFF + nwarp * (64 * BSTR) + lrow * BSTR + lkof * 2;

    float acc[32], outv[32];
#pragma unroll
    for (int i = 0; i < 32; ++i) { acc[i] = 0.f; outv[i] = 0.f; }

#pragma unroll
    for (int e = 0; e < 4; ++e) {
#pragma unroll
        for (int kc = 0; kc < 8; ++kc) {
            const int t = e * 8 + kc;        // compile-time in unrolled body
            // tail-exact waits: need chunk t complete before consuming
            if (t < 30)       asm volatile("cp.async.wait_group 2;" ::: "memory");
            else if (t == 30) asm volatile("cp.async.wait_group 1;" ::: "memory");
            else              asm volatile("cp.async.wait_group 0;" ::: "memory");
            __syncthreads();
            if (t < 29) {                    // prefetch chunk t+3 into stage (t+3)&3
                load_chunkB(bdst + ((t + 3) & 3) * SB_STAGE,
                            Whi + (size_t)(t + 3) * 8192,
                            Wlo + (size_t)(t + 3) * 8192, wsrc_off);
                asm volatile("cp.async.commit_group;" ::: "memory");
            }
            const uint32_t bS = bRow + (kc & 3) * SB_STAGE;  // static offset
#pragma unroll
            for (int ks = 0; ks < 2; ++ks) {
                uint32_t ah[4], al[4];
                const uint32_t ak = aBase + (kc * 32 + ks * 16) * 2;
                ldsm4(ah, ak);
                ldsm4(al, ak + SA_LO);
#pragma unroll
                for (int gpp = 0; gpp < 2; ++gpp) {
                    // two 16-col groups -> 4 independent acc tiles in flight
                    uint32_t bha[4], bla[4], bhb[4], blb[4];
                    const uint32_t ba = bS + gpp * (32 * BSTR) + ks * 32;
                    ldsm4(bha, ba);
                    ldsm4(bhb, ba + 16 * BSTR);
                    ldsm4(bla, ba + SB_LO);
                    ldsm4(blb, ba + SB_LO + 16 * BSTR);
                    float* A0 = acc + gpp * 16;
                    float* A1 = A0 + 4;
                    float* A2 = A0 + 8;
                    float* A3 = A0 + 12;
                    mma16816(A0, ah, bha[0], bha[2]);
                    mma16816(A1, ah, bha[1], bha[3]);
                    mma16816(A2, ah, bhb[0], bhb[2]);
                    mma16816(A3, ah, bhb[1], bhb[3]);
                    mma16816(A0, al, bha[0], bha[2]);
                    mma16816(A1, al, bha[1], bha[3]);
                    mma16816(A2, al, bhb[0], bhb[2]);
                    mma16816(A3, al, bhb[1], bhb[3]);
                    mma16816(A0, ah, bla[0], bla[2]);
                    mma16816(A1, ah, bla[1], bla[3]);
                    mma16816(A2, ah, blb[0], blb[2]);
                    mma16816(A3, ah, blb[1], blb[3]);
                }
            }
        }
        const float ce0 = (e == 0) ? cva.x : (e == 1) ? cva.y : (e == 2) ? cva.z : cva.w;
        const float ce1 = (e == 0) ? cvb.x : (e == 1) ? cvb.y : (e == 2) ? cvb.z : cvb.w;
#pragma unroll
        for (int i = 0; i < 32; i += 4) {
            outv[i]     += ce0 * acc[i];     acc[i]     = 0.f;
            outv[i + 1] += ce0 * acc[i + 1]; acc[i + 1] = 0.f;
            outv[i + 2] += ce1 * acc[i + 2]; acc[i + 2] = 0.f;
            outv[i + 3] += ce1 * acc[i + 3]; acc[i + 3] = 0.f;
        }
    }

    // ---- epilogue: + sum_e c_e * b_e[n], ReLU, store (f32 or bf16 hi/lo)
    const float* bsm = (const float*)(smem + SBIAS);
#pragma unroll
    for (int j = 0; j < 8; ++j) {            // 8 n8-tiles, acc base j*4
        const int nc = nwarp * 64 + j * 8 + (lane & 3) * 2;   // col within half
        const int n0 = colbase + nc;
        float b00 = cva.x * bsm[nc] + cva.y * bsm[128 + nc]
                  + cva.z * bsm[256 + nc] + cva.w * bsm[384 + nc];
        float b01 = cva.x * bsm[nc + 1] + cva.y * bsm[128 + nc + 1]
                  + cva.z * bsm[256 + nc + 1] + cva.w * bsm[384 + nc + 1];
        float b10 = cvb.x * bsm[nc] + cvb.y * bsm[128 + nc]
                  + cvb.z * bsm[256 + nc] + cvb.w * bsm[384 + nc];
        float b11 = cvb.x * bsm[nc + 1] + cvb.y * bsm[128 + nc + 1]
                  + cvb.z * bsm[256 + nc + 1] + cvb.w * bsm[384 + nc + 1];
        const float* o = outv + j * 4;
        float v0 = o[0] + b00, v1 = o[1] + b01;
        float v2 = o[2] + b10, v3 = o[3] + b11;
        if (RELU) {
            v0 = fmaxf(v0, 0.f); v1 = fmaxf(v1, 0.f);
            v2 = fmaxf(v2, 0.f); v3 = fmaxf(v3, 0.f);
        }
        if (BF16OUT) {
            unsigned short h0, l0, h1, l1, h2, l2, h3, l3;
            split_bf16(v0, h0, l0); split_bf16(v1, h1, l1);
            split_bf16(v2, h2, l2); split_bf16(v3, h3, l3);
            size_t p0 = (size_t)gr0 * NDIM + n0;
            size_t p1 = (size_t)(gr0 + 8) * NDIM + n0;
            *(uint32_t*)(Ohi + p0) = (uint32_t)h0 | ((uint32_t)h1 << 16);
            *(uint32_t*)(Olo + p0) = (uint32_t)l0 | ((uint32_t)l1 << 16);
            *(uint32_t*)(Ohi + p1) = (uint32_t)h2 | ((uint32_t)h3 << 16);
            *(uint32_t*)(Olo + p1) = (uint32_t)l2 | ((uint32_t)l3 << 16);
        } else {
            *(float2*)(Out + (size_t)gr0 * NDIM + n0)       = make_float2(v0, v1);
            *(float2*)(Out + (size_t)(gr0 + 8) * NDIM + n0) = make_float2(v2, v3);
        }
    }
}

// ---------------------------------------------------------------- launch
extern "C" void kernel_launch(void* const* d_in, const int* in_sizes, int n_in,
                              void* d_out, int out_size) {
    const float* X   = (const float*)d_in[0];
    const float* phi = (const float*)d_in[1];
    const float* W1  = (const float*)d_in[2];
    const float* b1  = (const float*)d_in[3];
    const float* W2  = (const float*)d_in[4];
    const float* b2  = (const float*)d_in[5];
    const float* W3  = (const float*)d_in[6];
    const float* b3  = (const float*)d_in[7];
    float* out = (float*)d_out;

    __nv_bfloat16 *Whi, *Wlo, *Ahi, *Alo, *Bhi, *Blo;
    cudaGetSymbolAddress((void**)&Whi, g_Whi);
    cudaGetSymbolAddress((void**)&Wlo, g_Wlo);
    cudaGetSymbolAddress((void**)&Ahi, g_Ahi);
    cudaGetSymbolAddress((void**)&Alo, g_Alo);
    cudaGetSymbolAddress((void**)&Bhi, g_Bhi);
    cudaGetSymbolAddress((void**)&Blo, g_Blo);

    cudaFuncSetAttribute(layer_hmma<true, true>,
                         cudaFuncAttributeMaxDynamicSharedMemorySize, SM_TOTAL);
    cudaFuncSetAttribute(layer_hmma<false, false>,
                         cudaFuncAttributeMaxDynamicSharedMemorySize, SM_TOTAL);

    coeff_kernel<<<BSZ / 256, 256>>>(phi);                 // launch 0
    convX_kernel<<<BSZ * NDIM / 1024, 256>>>(X);           // launch 1
    convW3_kernel<<<dim3(1024, 3), 256>>>(W1, W2, W3);     // launch 2

    // L1: A -> B   (launch 3)
    layer_hmma<true, true><<<1024, 512, SM_TOTAL>>>(
        Ahi, Alo, Whi, Wlo, b1, Bhi, Blo, nullptr);
    // L2: B -> A   (launch 4)
    layer_hmma<true, true><<<1024, 512, SM_TOTAL>>>(
        Bhi, Blo, Whi + 262144, Wlo + 262144, b2, Ahi, Alo, nullptr);
    // L3: A -> out (launch 5)
    layer_hmma<false, false><<<1024, 512, SM_TOTAL>>>(
        Ahi, Alo, Whi + 524288, Wlo + 524288, b3, nullptr, nullptr, out);
}

// round 17
// speedup vs baseline: 1.4552x; 1.4552x over previous
#include <cuda_runtime.h>
#include <cuda_bf16.h>
#include <cstdint>

// MotionPrediction: B=65536, 3 cyclic-MoE layers, dims 256, 4 experts.
// out = sum_e c_e (.) (X @ W_e + b_e), ReLU on layers 1,2.
// HMMA mma.sync m16n8k16 bf16 (volatile), hi/lo split (3 products).
// R15: R7 base + 2-chunk barrier groups with ALIAS-FREE distance-1 pair
// prefetch (group g consumes slots {2g&3,(2g+1)&3}, prefetches the OTHER pair).

#define BSZ  65536
#define NDIM 256

__device__ __align__(16) __nv_bfloat16 g_Whi[3 * 4 * NDIM * NDIM]; // [slot][chunk=e*8+kc][n256][k32]
__device__ __align__(16) __nv_bfloat16 g_Wlo[3 * 4 * NDIM * NDIM];
__device__ __align__(16) __nv_bfloat16 g_Ahi[BSZ * NDIM];
__device__ __align__(16) __nv_bfloat16 g_Alo[BSZ * NDIM];
__device__ __align__(16) __nv_bfloat16 g_Bhi[BSZ * NDIM];
__device__ __align__(16) __nv_bfloat16 g_Blo[BSZ * NDIM];
__device__ float4 g_coeff[BSZ];

// ---- SMEM map (bytes) ----
#define ASTR     528                    // A row stride (256 bf16 + pad)
#define SA_LO    67584                  // A_lo = A_hi + 128*528
#define SB_OFF   135168                 // 4 chunk slots
#define SB_STAGE 20480                  // per slot: hi 10240 + lo 10240
#define SB_LO    10240
#define BSTR     80                     // B row stride (32 bf16 + pad)
#define SBIAS    217088                 // 512 floats
#define SM_TOTAL 219136

// ---------------------------------------------------------------- helpers
__device__ __forceinline__ uint32_t smem_u32(const void* p) {
    uint32_t a;
    asm("{ .reg .u64 t; cvta.to.shared.u64 t, %1; cvt.u32.u64 %0, t; }"
        : "=r"(a) : "l"(p));
    return a;
}
__device__ __forceinline__ void ldsm4(uint32_t* r, uint32_t a) {
    asm volatile("ldmatrix.sync.aligned.m8n8.x4.shared.b16 {%0,%1,%2,%3}, [%4];"
                 : "=r"(r[0]), "=r"(r[1]), "=r"(r[2]), "=r"(r[3]) : "r"(a));
}
// volatile: measured load-bearing (R14 regression without it)
__device__ __forceinline__ void mma16816(float* d, const uint32_t* a,
                                         uint32_t b0, uint32_t b1) {
    asm volatile(
        "mma.sync.aligned.m16n8k16.row.col.f32.bf16.bf16.f32 "
        "{%0,%1,%2,%3}, {%4,%5,%6,%7}, {%8,%9}, {%0,%1,%2,%3};"
        : "+f"(d[0]), "+f"(d[1]), "+f"(d[2]), "+f"(d[3])
        : "r"(a[0]), "r"(a[1]), "r"(a[2]), "r"(a[3]), "r"(b0), "r"(b1));
}
__device__ __forceinline__ void cpa16(uint32_t s, const void* g) {
    asm volatile("cp.async.cg.shared.global [%0], [%1], 16;" :: "r"(s), "l"(g));
}
__device__ __forceinline__ void split_bf16(float v, unsigned short& h, unsigned short& l) {
    __nv_bfloat16 hb = __float2bfloat16_rn(v);
    float r = v - __bfloat162float(hb);
    h = __bfloat16_as_ushort(hb);
    l = __bfloat16_as_ushort(__float2bfloat16_rn(r));
}

// ---------------------------------------------------------------- coeff
__global__ void coeff_kernel(const float* __restrict__ phi) {
    int b = blockIdx.x * blockDim.x + threadIdx.x;
    if (b >= BSZ) return;
    const float TWO_OVER_PI = (float)(2.0 / 3.14159265358979323846);
    float w  = TWO_OVER_PI * phi[b];
    int  wi  = ((int)w) & 3;
    float w2 = w * w, w3 = w2 * w;
    float co[4];
    co[0] = -0.5f * w + w2 - 0.5f * w3;
    co[1] = -2.5f * w2 + 1.5f * w3;
    co[2] =  0.5f * w + 2.0f * w2 - 1.5f * w3;
    co[3] = -0.5f * w2 + 0.5f * w3;
    float c[4];
#pragma unroll
    for (int e = 0; e < 4; ++e) c[e] = co[(e - wi + 5) & 3];
    g_coeff[b] = make_float4(c[0], c[1], c[2], c[3]);
}

// ---------------------------------------------------------------- X convert
__global__ void convX_kernel(const float* __restrict__ X) {
    size_t i = ((size_t)blockIdx.x * 256 + threadIdx.x) * 4;
    float4 f = *(const float4*)(X + i);
    float v[4] = {f.x, f.y, f.z, f.w};
    unsigned short h[4], l[4];
#pragma unroll
    for (int p = 0; p < 4; ++p) split_bf16(v[p], h[p], l[p]);
    *(uint2*)(g_Ahi + i) = make_uint2((uint32_t)h[0] | ((uint32_t)h[1] << 16),
                                      (uint32_t)h[2] | ((uint32_t)h[3] << 16));
    *(uint2*)(g_Alo + i) = make_uint2((uint32_t)l[0] | ((uint32_t)l[1] << 16),
                                      (uint32_t)l[2] | ((uint32_t)l[3] << 16));
}

// ---------------------------------------------------------------- W convert
// W [4][256 k][256 n] f32 -> blocked [chunk=e*8+kc][n 256][k 32] bf16 hi/lo
__global__ void convW3_kernel(const float* __restrict__ Wa,
                              const float* __restrict__ Wb,
                              const float* __restrict__ Wc) {
    int i = blockIdx.x * 256 + threadIdx.x;     // 262144 per layer
    int slot = blockIdx.y;
    const float* W = (slot == 0) ? Wa : (slot == 1) ? Wb : Wc;
    int chunk = i >> 13;
    int n = (i >> 5) & 255;
    int k = i & 31;
    int e = chunk >> 3, kc = chunk & 7;
    float w = W[((e << 8) + kc * 32 + k) * NDIM + n];
    unsigned short h, l;
    split_bf16(w, h, l);
    g_Whi[(size_t)slot * 262144 + i] = __ushort_as_bfloat16(h);
    g_Wlo[(size_t)slot * 262144 + i] = __ushort_as_bfloat16(l);
}

// ---------------------------------------------------------------- B chunk load
__device__ __forceinline__ void load_chunkB(uint32_t dst,
                                            const __nv_bfloat16* __restrict__ sH,
                                            const __nv_bfloat16* __restrict__ sL,
                                            uint32_t soff) {
    cpa16(dst,         (const char*)sH + soff);
    cpa16(dst + SB_LO, (const char*)sL + soff);
}

// ---------------------------------------------------------------- layer
template <bool RELU, bool BF16OUT>
__global__ void __launch_bounds__(512, 1) layer_hmma(
    const __nv_bfloat16* __restrict__ Xhi,
    const __nv_bfloat16* __restrict__ Xlo,
    const __nv_bfloat16* __restrict__ Whi,
    const __nv_bfloat16* __restrict__ Wlo,
    const float* __restrict__ bias,
    __nv_bfloat16* __restrict__ Ohi,
    __nv_bfloat16* __restrict__ Olo,
    float* __restrict__ Out)
{
    extern __shared__ char smem[];
    const uint32_t sb = smem_u32(smem);
    const int tid = threadIdx.x, lane = tid & 31, wid = tid >> 5;
    const int mwarp = wid >> 1, nwarp = wid & 1;   // 8 M-warps x 2 N-warps
    const int mtile = blockIdx.x >> 1, ch = blockIdx.x & 1;
    const int rowbase = mtile << 7, colbase = ch << 7;

    // per-thread source offset within a W chunk (bytes): row (colbase+n), quad q
    const int bn = tid >> 2, bq = tid & 3;
    const uint32_t wsrc_off = (uint32_t)(colbase + bn) * 64 + bq * 16;
    const uint32_t bdst = sb + SB_OFF + bn * BSTR + bq * 16;   // + slot*SB_STAGE

    // A tile: 128 rows x 256 bf16 hi/lo via cp.async (group 0)
#pragma unroll
    for (int u = tid; u < 4096; u += 512) {
        int r = u >> 5, s = u & 31;
        cpa16(sb + r * ASTR + s * 16,         Xhi + (size_t)(rowbase + r) * NDIM + s * 8);
        cpa16(sb + SA_LO + r * ASTR + s * 16, Xlo + (size_t)(rowbase + r) * NDIM + s * 8);
    }
    asm volatile("cp.async.commit_group;" ::: "memory");
    // preload pair 0 (chunks 0,1) into slots 0,1 — one commit
    load_chunkB(bdst,            Whi,        Wlo,        wsrc_off);
    load_chunkB(bdst + SB_STAGE, Whi + 8192, Wlo + 8192, wsrc_off);
    asm volatile("cp.async.commit_group;" ::: "memory");

    // bias -> smem: [e][128] for this col half
    ((float*)(smem + SBIAS))[tid] = bias[(tid >> 7) * NDIM + colbase + (tid & 127)];

    const int gr0 = rowbase + mwarp * 16 + (lane >> 2);
    const float4 cva = g_coeff[gr0];
    const float4 cvb = g_coeff[gr0 + 8];

    const int lrow = (lane & 7) + (((lane >> 3) & 1) << 3);
    const int lkof = (lane >> 4) << 3;
    const uint32_t aBase = sb + (mwarp * 16 + lrow) * ASTR + lkof * 2;
    const uint32_t bRow  = sb + SB_OFF + nwarp * (64 * BSTR) + lrow * BSTR + lkof * 2;

    float acc[32], outv[32];
#pragma unroll
    for (int i = 0; i < 32; ++i) { acc[i] = 0.f; outv[i] = 0.f; }

#pragma unroll
    for (int g = 0; g < 16; ++g) {           // 2 chunks per barrier group
        asm volatile("cp.async.wait_group 0;" ::: "memory");  // pair g landed
        __syncthreads();
        if (g < 15) {
            // prefetch pair g+1 (chunks 2g+2, 2g+3) into the OTHER slot pair:
            // consumed slots this group = {(2g)&3, (2g+1)&3}; targets differ.
            const int c0 = 2 * g + 2;
            load_chunkB(bdst + (c0 & 3) * SB_STAGE,
                        Whi + (size_t)c0 * 8192, Wlo + (size_t)c0 * 8192, wsrc_off);
            load_chunkB(bdst + ((c0 + 1) & 3) * SB_STAGE,
                        Whi + (size_t)(c0 + 1) * 8192, Wlo + (size_t)(c0 + 1) * 8192,
                        wsrc_off);
            asm volatile("cp.async.commit_group;" ::: "memory");
        }
#pragma unroll
        for (int cc = 0; cc < 2; ++cc) {
            const int t = 2 * g + cc;        // compile-time in unrolled body
            const int kc = t & 7;
            const uint32_t bS = bRow + (t & 3) * SB_STAGE;
#pragma unroll
            for (int ks = 0; ks < 2; ++ks) {
                uint32_t ah[4], al[4];
                const uint32_t ak = aBase + (kc * 32 + ks * 16) * 2;
                ldsm4(ah, ak);
                ldsm4(al, ak + SA_LO);
#pragma unroll
                for (int gpp = 0; gpp < 2; ++gpp) {
                    // two 16-col groups -> 4 independent acc tiles in flight
                    uint32_t bha[4], bla[4], bhb[4], blb[4];
                    const uint32_t ba = bS + gpp * (32 * BSTR) + ks * 32;
                    ldsm4(bha, ba);
                    ldsm4(bhb, ba + 16 * BSTR);
                    ldsm4(bla, ba + SB_LO);
                    ldsm4(blb, ba + SB_LO + 16 * BSTR);
                    float* A0 = acc + gpp * 16;
                    float* A1 = A0 + 4;
                    float* A2 = A0 + 8;
                    float* A3 = A0 + 12;
                    mma16816(A0, ah, bha[0], bha[2]);
                    mma16816(A1, ah, bha[1], bha[3]);
                    mma16816(A2, ah, bhb[0], bhb[2]);
                    mma16816(A3, ah, bhb[1], bhb[3]);
                    mma16816(A0, al, bha[0], bha[2]);
                    mma16816(A1, al, bha[1], bha[3]);
                    mma16816(A2, al, bhb[0], bhb[2]);
                    mma16816(A3, al, bhb[1], bhb[3]);
                    mma16816(A0, ah, bla[0], bla[2]);
                    mma16816(A1, ah, bla[1], bla[3]);
                    mma16816(A2, ah, blb[0], blb[2]);
                    mma16816(A3, ah, blb[1], blb[3]);
                }
            }
        }
        if ((g & 3) == 3) {                  // expert boundary: fold e = g>>2
            const int e = g >> 2;
            const float ce0 = (e == 0) ? cva.x : (e == 1) ? cva.y : (e == 2) ? cva.z : cva.w;
            const float ce1 = (e == 0) ? cvb.x : (e == 1) ? cvb.y : (e == 2) ? cvb.z : cvb.w;
#pragma unroll
            for (int i = 0; i < 32; i += 4) {
                outv[i]     += ce0 * acc[i];     acc[i]     = 0.f;
                outv[i + 1] += ce0 * acc[i + 1]; acc[i + 1] = 0.f;
                outv[i + 2] += ce1 * acc[i + 2]; acc[i + 2] = 0.f;
                outv[i + 3] += ce1 * acc[i + 3]; acc[i + 3] = 0.f;
            }
        }
    }

    // ---- epilogue: + sum_e c_e * b_e[n], ReLU, store (f32 or bf16 hi/lo)
    const float* bsm = (const float*)(smem + SBIAS);
#pragma unroll
    for (int j = 0; j < 8; ++j) {            // 8 n8-tiles, acc base j*4
        const int nc = nwarp * 64 + j * 8 + (lane & 3) * 2;   // col within half
        const int n0 = colbase + nc;
        float b00 = cva.x * bsm[nc] + cva.y * bsm[128 + nc]
                  + cva.z * bsm[256 + nc] + cva.w * bsm[384 + nc];
        float b01 = cva.x * bsm[nc + 1] + cva.y * bsm[128 + nc + 1]
                  + cva.z * bsm[256 + nc + 1] + cva.w * bsm[384 + nc + 1];
        float b10 = cvb.x * bsm[nc] + cvb.y * bsm[128 + nc]
                  + cvb.z * bsm[256 + nc] + cvb.w * bsm[384 + nc];
        float b11 = cvb.x * bsm[nc + 1] + cvb.y * bsm[128 + nc + 1]
                  + cvb.z * bsm[256 + nc + 1] + cvb.w * bsm[384 + nc + 1];
        const float* o = outv + j * 4;
        float v0 = o[0] + b00, v1 = o[1] + b01;
        float v2 = o[2] + b10, v3 = o[3] + b11;
        if (RELU) {
            v0 = fmaxf(v0, 0.f); v1 = fmaxf(v1, 0.f);
            v2 = fmaxf(v2, 0.f); v3 = fmaxf(v3, 0.f);
        }
        if (BF16OUT) {
            unsigned short h0, l0, h1, l1, h2, l2, h3, l3;
            split_bf16(v0, h0, l0); split_bf16(v1, h1, l1);
            split_bf16(v2, h2, l2); split_bf16(v3, h3, l3);
            size_t p0 = (size_t)gr0 * NDIM + n0;
            size_t p1 = (size_t)(gr0 + 8) * NDIM + n0;
            *(uint32_t*)(Ohi + p0) = (uint32_t)h0 | ((uint32_t)h1 << 16);
            *(uint32_t*)(Olo + p0) = (uint32_t)l0 | ((uint32_t)l1 << 16);
            *(uint32_t*)(Ohi + p1) = (uint32_t)h2 | ((uint32_t)h3 << 16);
            *(uint32_t*)(Olo + p1) = (uint32_t)l2 | ((uint32_t)l3 << 16);
        } else {
            *(float2*)(Out + (size_t)gr0 * NDIM + n0)       = make_float2(v0, v1);
            *(float2*)(Out + (size_t)(gr0 + 8) * NDIM + n0) = make_float2(v2, v3);
        }
    }
}

// ---------------------------------------------------------------- launch
extern "C" void kernel_launch(void* const* d_in, const int* in_sizes, int n_in,
                              void* d_out, int out_size) {
    const float* X   = (const float*)d_in[0];
    const float* phi = (const float*)d_in[1];
    const float* W1  = (const float*)d_in[2];
    const float* b1  = (const float*)d_in[3];
    const float* W2  = (const float*)d_in[4];
    const float* b2  = (const float*)d_in[5];
    const float* W3  = (const float*)d_in[6];
    const float* b3  = (const float*)d_in[7];
    float* out = (float*)d_out;

    __nv_bfloat16 *Whi, *Wlo, *Ahi, *Alo, *Bhi, *Blo;
    cudaGetSymbolAddress((void**)&Whi, g_Whi);
    cudaGetSymbolAddress((void**)&Wlo, g_Wlo);
    cudaGetSymbolAddress((void**)&Ahi, g_Ahi);
    cudaGetSymbolAddress((void**)&Alo, g_Alo);
    cudaGetSymbolAddress((void**)&Bhi, g_Bhi);
    cudaGetSymbolAddress((void**)&Blo, g_Blo);

    cudaFuncSetAttribute(layer_hmma<true, true>,
                         cudaFuncAttributeMaxDynamicSharedMemorySize, SM_TOTAL);
    cudaFuncSetAttribute(layer_hmma<false, false>,
                         cudaFuncAttributeMaxDynamicSharedMemorySize, SM_TOTAL);

    coeff_kernel<<<BSZ / 256, 256>>>(phi);                 // launch 0
    convX_kernel<<<BSZ * NDIM / 1024, 256>>>(X);           // launch 1
    convW3_kernel<<<dim3(1024, 3), 256>>>(W1, W2, W3);     // launch 2

    // L1: A -> B   (launch 3)
    layer_hmma<true, true><<<1024, 512, SM_TOTAL>>>(
        Ahi, Alo, Whi, Wlo, b1, Bhi, Blo, nullptr);
    // L2: B -> A   (launch 4)
    layer_hmma<true, true><<<1024, 512, SM_TOTAL>>>(
        Bhi, Blo, Whi + 262144, Wlo + 262144, b2, Ahi, Alo, nullptr);
    // L3: A -> out (launch 5)
    layer_hmma<false, false><<<1024, 512, SM_TOTAL>>>(
        Ahi, Alo, Whi + 524288, Wlo + 524288, b3, nullptr, nullptr, out);
}